// round 10
// baseline (speedup 1.0000x reference)
#include <cuda_runtime.h>
#include <cuda_bf16.h>
#include <cstdint>

// Problem constants
#define BB    2
#define SS    2048
#define DD    1024
#define HH    16
#define DHh   64
#define FFD   4096
#define BSR   (BB*SS)          // 4096 rows
#define QC    256              // query-chunk rows per attention pass
#define NCHUNK (SS/QC)         // 8

// ---------------- static scratch (no allocation; ~240MB, proven OK) ----------
__device__ float g_Q  [BB*SS*DD];
__device__ float g_K  [BB*SS*DD];
__device__ float g_V  [BB*SS*DD];
__device__ float g_Sc [BB*HH*QC*SS];       // 64 MB score chunk
__device__ float g_ctx[BB*SS*DD];
__device__ float g_ar [BB*SS*DD];
__device__ float g_y  [BB*SS*DD];
__device__ float g_h  [BB*SS*FFD];
__device__ float g_z  [BB*SS*DD];

// ---------------- helpers ----------------
__device__ __forceinline__ void tf32split(float x, uint32_t& hi, uint32_t& lo)
{
    uint32_t h;
    asm("cvt.rna.tf32.f32 %0, %1;" : "=r"(h) : "f"(x));
    float hf = __uint_as_float(h);
    float r  = x - hf;                 // exact: hi has zeroed low mantissa bits
    uint32_t l;
    asm("cvt.rna.tf32.f32 %0, %1;" : "=r"(l) : "f"(r));
    hi = h; lo = l;
}

__device__ __forceinline__ void mma8(float* d, const uint32_t* a, const uint32_t* b)
{
    asm volatile(
        "mma.sync.aligned.m16n8k8.row.col.f32.tf32.tf32.f32 "
        "{%0,%1,%2,%3},{%4,%5,%6,%7},{%8,%9},{%0,%1,%2,%3};"
        : "+f"(d[0]), "+f"(d[1]), "+f"(d[2]), "+f"(d[3])
        : "r"(a[0]), "r"(a[1]), "r"(a[2]), "r"(a[3]), "r"(b[0]), "r"(b[1]));
}

__device__ __forceinline__ void cpasync16(uint32_t dst_smem, const float* src)
{
    asm volatile("cp.async.cg.shared.global [%0], [%1], 16;\n"
                 :: "r"(dst_smem), "l"((unsigned long long)(uintptr_t)src)
                 : "memory");
}
__device__ __forceinline__ void cpasync_commit()
{
    asm volatile("cp.async.commit_group;\n" ::: "memory");
}
__device__ __forceinline__ void cpasync_wait_all()
{
    asm volatile("cp.async.wait_group 0;\n" ::: "memory");
}

// ---------------- tensor-core GEMM: cp.async 2-stage, split-at-fragment ------
// C[M,N] = epilogue( alpha * A[M,K] * op(B) )
// BT=true : B is [N,K] row-major (NT gemm: A @ B^T). BT=false: B is [K,N] (NN).
// Smem: A raw fp32 [m][k] stride BK+4. B: NT -> [n][k] stride BK+4 (conflict-free),
//       NN -> [k][n] stride BN+8 (conflict-free; cp.async chunks are n-contiguous).
// tf32 hi/lo split happens in registers at fragment-load time (3 MMAs/product).
// 256 threads = 8 warps; warp grid (BM/WM) x (BN/WN) == 8. BK must be 16.
template<int BM,int BN,int BK,int WM,int WN,bool BT,bool RELU,bool BIAS,bool RES>
__global__ __launch_bounds__(256,1)
void mgemm_k(const float* __restrict__ A, int lda,
             const float* __restrict__ Bm, int ldb,
             float*       __restrict__ C,  int ldc,
             int K, float alpha,
             const float* __restrict__ bias,
             const float* __restrict__ res,
             int zdiv,
             long soA, long siA, long soB, long siB, long soC, long siC)
{
    constexpr int SDA = BK + 4;
    constexpr int SDB = BT ? (BK + 4) : (BN + 8);
    constexpr int ASZ = BM * SDA;
    constexpr int BSZ = BT ? (BN * SDB) : (BK * SDB);
    constexpr int MT  = WM / 16;
    constexpr int NT2 = WN / 8;
    constexpr int MW  = BM / WM;
    constexpr int KV  = BK / 4;
    constexpr int NAc = (BM * KV) / 256;                       // 16B chunks/thread, A
    constexpr int NBc = BT ? (BN * KV) / 256 : (BK * (BN/4)) / 256;

    __shared__ float sA[2*ASZ];
    __shared__ float sB[2*BSZ];

    const int z  = blockIdx.z;
    const long zo = z / zdiv, zi = z % zdiv;
    A  += zo*soA + zi*siA;
    Bm += zo*soB + zi*siB;
    C  += zo*soC + zi*siC;

    const int tid    = threadIdx.x;
    const int lane   = tid & 31;
    const int warpId = tid >> 5;
    const int wm     = warpId % MW;
    const int wn     = warpId / MW;
    const int r      = lane >> 2;
    const int c      = lane & 3;
    const int rowBase = blockIdx.y * BM;
    const int colBase = blockIdx.x * BN;

    const uint32_t sAaddr = (uint32_t)__cvta_generic_to_shared(sA);
    const uint32_t sBaddr = (uint32_t)__cvta_generic_to_shared(sB);

    // per-thread chunk coordinates
    int aR[NAc], aK[NAc];
    #pragma unroll
    for (int j = 0; j < NAc; j++) {
        int i = tid + j*256;
        aR[j] = i / KV; aK[j] = (i % KV) * 4;
    }
    int bR[NBc], bK[NBc];   // BT: (n-row, k-off)   NN: (k-row, n-off)
    #pragma unroll
    for (int j = 0; j < NBc; j++) {
        int i = tid + j*256;
        if (BT) { bR[j] = i / KV;       bK[j] = (i % KV) * 4; }
        else    { bR[j] = i / (BN/4);   bK[j] = (i % (BN/4)) * 4; }
    }

    float acc[MT][NT2][4];
    #pragma unroll
    for (int im = 0; im < MT; im++)
        #pragma unroll
        for (int in = 0; in < NT2; in++)
            #pragma unroll
            for (int q = 0; q < 4; q++) acc[im][in][q] = 0.f;

    const int nT = K / BK;

    // ---- prologue: issue tile 0 into stage 0 ----
    #pragma unroll
    for (int j = 0; j < NAc; j++)
        cpasync16(sAaddr + (aR[j]*SDA + aK[j])*4,
                  A + (long)(rowBase + aR[j])*lda + aK[j]);
    #pragma unroll
    for (int j = 0; j < NBc; j++) {
        if (BT)
            cpasync16(sBaddr + (bR[j]*SDB + bK[j])*4,
                      Bm + (long)(colBase + bR[j])*ldb + bK[j]);
        else
            cpasync16(sBaddr + (bR[j]*SDB + bK[j])*4,
                      Bm + (long)(bR[j])*ldb + (colBase + bK[j]));
    }
    cpasync_commit();

    for (int t = 0; t < nT; t++) {
        cpasync_wait_all();
        __syncthreads();

        // issue next tile into the other stage (overlaps compute below)
        if (t + 1 < nT) {
            const int kn = (t + 1) * BK;
            const uint32_t stOff = ((t + 1) & 1) ? 1u : 0u;
            const uint32_t aBase = sAaddr + stOff*ASZ*4;
            const uint32_t bBase = sBaddr + stOff*BSZ*4;
            #pragma unroll
            for (int j = 0; j < NAc; j++)
                cpasync16(aBase + (aR[j]*SDA + aK[j])*4,
                          A + (long)(rowBase + aR[j])*lda + (kn + aK[j]));
            #pragma unroll
            for (int j = 0; j < NBc; j++) {
                if (BT)
                    cpasync16(bBase + (bR[j]*SDB + bK[j])*4,
                              Bm + (long)(colBase + bR[j])*ldb + (kn + bK[j]));
                else
                    cpasync16(bBase + (bR[j]*SDB + bK[j])*4,
                              Bm + (long)(kn + bR[j])*ldb + (colBase + bK[j]));
            }
            cpasync_commit();
        }

        // ---- compute on stage t&1 ----
        const float* sAb = sA + (t & 1) * ASZ;
        const float* sBb = sB + (t & 1) * BSZ;

        #pragma unroll
        for (int ks = 0; ks < BK/8; ks++) {
            const int kb = ks * 8;
            uint32_t afh[MT][4], afl[MT][4], bfh[NT2][2], bfl[NT2][2];
            #pragma unroll
            for (int im = 0; im < MT; im++) {
                const int mb = wm*WM + im*16;
                float a0 = sAb[(mb+r  )*SDA + kb + c    ];
                float a1 = sAb[(mb+r+8)*SDA + kb + c    ];
                float a2 = sAb[(mb+r  )*SDA + kb + c + 4];
                float a3 = sAb[(mb+r+8)*SDA + kb + c + 4];
                tf32split(a0, afh[im][0], afl[im][0]);
                tf32split(a1, afh[im][1], afl[im][1]);
                tf32split(a2, afh[im][2], afl[im][2]);
                tf32split(a3, afh[im][3], afl[im][3]);
            }
            #pragma unroll
            for (int in = 0; in < NT2; in++) {
                const int nb = wn*WN + in*8;
                float b0, b1;
                if (BT) {
                    b0 = sBb[(nb+r)*SDB + kb + c    ];
                    b1 = sBb[(nb+r)*SDB + kb + c + 4];
                } else {
                    b0 = sBb[(kb + c    )*SDB + nb + r];
                    b1 = sBb[(kb + c + 4)*SDB + nb + r];
                }
                tf32split(b0, bfh[in][0], bfl[in][0]);
                tf32split(b1, bfh[in][1], bfl[in][1]);
            }
            #pragma unroll
            for (int im = 0; im < MT; im++)
                #pragma unroll
                for (int in = 0; in < NT2; in++) {
                    mma8(acc[im][in], afh[im], bfh[in]);  // hi*hi
                    mma8(acc[im][in], afh[im], bfl[in]);  // hi*lo
                    mma8(acc[im][in], afl[im], bfh[in]);  // lo*hi
                }
        }
    }

    // ---- epilogue ----
    #pragma unroll
    for (int im = 0; im < MT; im++) {
        #pragma unroll
        for (int in = 0; in < NT2; in++) {
            const long row0 = rowBase + wm*WM + im*16 + r;
            const long row1 = row0 + 8;
            const int  col  = colBase + wn*WN + in*8 + 2*c;
            float2 d0 = make_float2(acc[im][in][0]*alpha, acc[im][in][1]*alpha);
            float2 d1 = make_float2(acc[im][in][2]*alpha, acc[im][in][3]*alpha);
            if (BIAS) {
                float2 bv = *(const float2*)(bias + col);
                d0.x += bv.x; d0.y += bv.y; d1.x += bv.x; d1.y += bv.y;
            }
            if (RES) {
                float2 r0 = *(const float2*)(res + row0*(long)ldc + col);
                float2 r1 = *(const float2*)(res + row1*(long)ldc + col);
                d0.x += r0.x; d0.y += r0.y; d1.x += r1.x; d1.y += r1.y;
            }
            if (RELU) {
                d0.x = fmaxf(d0.x, 0.f); d0.y = fmaxf(d0.y, 0.f);
                d1.x = fmaxf(d1.x, 0.f); d1.y = fmaxf(d1.y, 0.f);
            }
            *(float2*)(C + row0*(long)ldc + col) = d0;
            *(float2*)(C + row1*(long)ldc + col) = d1;
        }
    }
}

// ---------------- softmax over rows of length 2048 (input already relu'd) ----
__global__ void softmax_k(float* __restrict__ Sc)
{
    const long row = blockIdx.x;
    float* p = Sc + row * (long)SS;
    const int tid = threadIdx.x;
    float4 v0 = ((const float4*)p)[tid];
    float4 v1 = ((const float4*)p)[tid + 256];

    float m = fmaxf(fmaxf(fmaxf(v0.x,v0.y), fmaxf(v0.z,v0.w)),
                    fmaxf(fmaxf(v1.x,v1.y), fmaxf(v1.z,v1.w)));
    #pragma unroll
    for (int o = 16; o; o >>= 1) m = fmaxf(m, __shfl_xor_sync(0xffffffffu, m, o));

    __shared__ float smax[8], ssum[8];
    const int wid = tid >> 5, lid = tid & 31;
    if (lid == 0) smax[wid] = m;
    __syncthreads();
    m = smax[0];
    #pragma unroll
    for (int i = 1; i < 8; i++) m = fmaxf(m, smax[i]);

    float e[8];
    e[0]=__expf(v0.x-m); e[1]=__expf(v0.y-m); e[2]=__expf(v0.z-m); e[3]=__expf(v0.w-m);
    e[4]=__expf(v1.x-m); e[5]=__expf(v1.y-m); e[6]=__expf(v1.z-m); e[7]=__expf(v1.w-m);
    float s = ((e[0]+e[1])+(e[2]+e[3])) + ((e[4]+e[5])+(e[6]+e[7]));
    #pragma unroll
    for (int o = 16; o; o >>= 1) s += __shfl_xor_sync(0xffffffffu, s, o);
    if (lid == 0) ssum[wid] = s;
    __syncthreads();
    s = ssum[0];
    #pragma unroll
    for (int i = 1; i < 8; i++) s += ssum[i];

    const float inv = 1.0f / s;
    ((float4*)p)[tid]       = make_float4(e[0]*inv, e[1]*inv, e[2]*inv, e[3]*inv);
    ((float4*)p)[tid + 256] = make_float4(e[4]*inv, e[5]*inv, e[6]*inv, e[7]*inv);
}

// ---------------- layernorm over rows of length 1024 ----------------
__global__ void ln_k(const float* __restrict__ in, float* __restrict__ out,
                     const float* __restrict__ gw, const float* __restrict__ bw)
{
    const long row = blockIdx.x;
    const float* p = in + row * (long)DD;
    const int tid = threadIdx.x;
    float4 v = ((const float4*)p)[tid];
    float s = v.x + v.y + v.z + v.w;
    float q = v.x*v.x + v.y*v.y + v.z*v.z + v.w*v.w;
    #pragma unroll
    for (int o = 16; o; o >>= 1) {
        s += __shfl_xor_sync(0xffffffffu, s, o);
        q += __shfl_xor_sync(0xffffffffu, q, o);
    }
    __shared__ float ss[8], qq[8];
    const int wid = tid >> 5, lid = tid & 31;
    if (lid == 0) { ss[wid] = s; qq[wid] = q; }
    __syncthreads();
    float S = 0.f, Q = 0.f;
    #pragma unroll
    for (int i = 0; i < 8; i++) { S += ss[i]; Q += qq[i]; }

    const float mean = S * (1.0f / DD);
    const float var  = Q * (1.0f / DD) - mean * mean;
    const float inv  = rsqrtf(var + 1e-5f);

    float4 g4 = ((const float4*)gw)[tid];
    float4 b4 = ((const float4*)bw)[tid];
    float4 o;
    o.x = (v.x - mean) * inv * g4.x + b4.x;
    o.y = (v.y - mean) * inv * g4.y + b4.y;
    o.z = (v.z - mean) * inv * g4.z + b4.z;
    o.w = (v.w - mean) * inv * g4.w + b4.w;
    ((float4*)(out + row * (long)DD))[tid] = o;
}

// ---------------- launch ----------------
extern "C" void kernel_launch(void* const* d_in, const int* in_sizes, int n_in,
                              void* d_out, int out_size)
{
    const float* X   = (const float*)d_in[0];
    const float* Wq  = (const float*)d_in[1];
    const float* Wk  = (const float*)d_in[2];
    const float* Wo  = (const float*)d_in[3];
    const float* l1g = (const float*)d_in[4];
    const float* l1b = (const float*)d_in[5];
    const float* l2g = (const float*)d_in[6];
    const float* l2b = (const float*)d_in[7];
    const float* W1  = (const float*)d_in[8];
    const float* b1  = (const float*)d_in[9];
    const float* W2  = (const float*)d_in[10];
    const float* b2  = (const float*)d_in[11];
    float* out = (float*)d_out;

    float *Q, *K, *V, *Sc, *CT, *AR, *Y, *Hh, *Z;
    cudaGetSymbolAddress((void**)&Q,  g_Q);
    cudaGetSymbolAddress((void**)&K,  g_K);
    cudaGetSymbolAddress((void**)&V,  g_V);
    cudaGetSymbolAddress((void**)&Sc, g_Sc);
    cudaGetSymbolAddress((void**)&CT, g_ctx);
    cudaGetSymbolAddress((void**)&AR, g_ar);
    cudaGetSymbolAddress((void**)&Y,  g_y);
    cudaGetSymbolAddress((void**)&Hh, g_h);
    cudaGetSymbolAddress((void**)&Z,  g_z);

    const dim3 blk(256);
    const dim3 gproj(DD/128,  BSR/128, 1);
    const dim3 gscC (SS/128,  QC/128,  BB*HH);
    const dim3 gctxC(DHh/64,  QC/64,   BB*HH);
    const dim3 gf1  (FFD/128, BSR/128, 1);

    // --- QKV projections: Q/K = X@Wq^T / X@Wk^T, V = X@Wo^T ---
    mgemm_k<128,128,16,64,32,true,false,false,false><<<gproj, blk>>>(
        X, DD, Wq, DD, Q, DD, DD, 1.f, nullptr, nullptr, 1, 0,0,0,0,0,0);
    mgemm_k<128,128,16,64,32,true,false,false,false><<<gproj, blk>>>(
        X, DD, Wk, DD, K, DD, DD, 1.f, nullptr, nullptr, 1, 0,0,0,0,0,0);
    mgemm_k<128,128,16,64,32,true,false,false,false><<<gproj, blk>>>(
        X, DD, Wo, DD, V, DD, DD, 1.f, nullptr, nullptr, 1, 0,0,0,0,0,0);

    // --- attention, chunked over query rows ---
    for (int cch = 0; cch < NCHUNK; cch++) {
        // scores chunk: relu(Q[c] @ K^T / 8), batched over (b,h)
        mgemm_k<128,128,16,64,32,true,true,false,false><<<gscC, blk>>>(
            Q + (long)cch*QC*DD, DD, K, DD, Sc, SS, DHh, 0.125f, nullptr, nullptr,
            HH, (long)SS*DD, (long)DHh,
                (long)SS*DD, (long)DHh,
                (long)HH*QC*SS, (long)QC*SS);

        softmax_k<<<BB*HH*QC, 256>>>(Sc);

        // ctx chunk = attn[c] @ V_h  (NN gemm, N=64)
        mgemm_k<64,64,16,32,16,false,false,false,false><<<gctxC, blk>>>(
            Sc, SS, V, DD, CT + (long)cch*QC*DD, DD, SS, 1.f, nullptr, nullptr,
            HH, (long)HH*QC*SS, (long)QC*SS,
                (long)SS*DD, (long)DHh,
                (long)SS*DD, (long)DHh);
    }

    // --- out-proj + residual X ---
    mgemm_k<128,128,16,64,32,true,false,false,true><<<gproj, blk>>>(
        CT, DD, Wo, DD, AR, DD, DD, 1.f, nullptr, X, 1, 0,0,0,0,0,0);

    ln_k<<<BSR, 256>>>(AR, Y, l1g, l1b);

    // --- FFN1: relu(y @ W1^T + b1) ---
    mgemm_k<128,128,16,64,32,true,true,true,false><<<gf1, blk>>>(
        Y, DD, W1, DD, Hh, FFD, DD, 1.f, b1, nullptr, 1, 0,0,0,0,0,0);

    // --- FFN2: h @ W2^T + b2 + y ---
    mgemm_k<128,128,16,64,32,true,false,true,true><<<gproj, blk>>>(
        Hh, FFD, W2, FFD, Z, DD, FFD, 1.f, b2, Y, 1, 0,0,0,0,0,0);

    ln_k<<<BSR, 256>>>(Z, out, l2g, l2b);
}

// round 11
// speedup vs baseline: 2.1074x; 2.1074x over previous
#include <cuda_runtime.h>
#include <cuda_bf16.h>
#include <cstdint>

// Problem constants
#define BB    2
#define SS    2048
#define DD    1024
#define HH    16
#define DHh   64
#define FFD   4096
#define BSR   (BB*SS)          // 4096 rows
#define QC    256              // query-chunk rows per attention pass
#define NCHUNK (SS/QC)         // 8

// ---------------- static scratch (no allocation; ~240MB, proven OK) ----------
__device__ float g_Q  [BB*SS*DD];
__device__ float g_K  [BB*SS*DD];
__device__ float g_V  [BB*SS*DD];
__device__ float g_Sc [BB*HH*QC*SS];       // 64 MB score chunk
__device__ float g_ctx[BB*SS*DD];
__device__ float g_ar [BB*SS*DD];
__device__ float g_y  [BB*SS*DD];
__device__ float g_h  [BB*SS*FFD];
__device__ float g_z  [BB*SS*DD];

// ================= bf16 split helpers =================
// x0,x1 -> packed bf16x2 hi pair + packed bf16x2 residual pair (lo in low half)
__device__ __forceinline__ void bsplit2(float x0, float x1, uint32_t& hp, uint32_t& lp)
{
    asm("cvt.rn.bf16x2.f32 %0, %1, %2;" : "=r"(hp) : "f"(x1), "f"(x0));
    float h0 = __uint_as_float(hp << 16);
    float h1 = __uint_as_float(hp & 0xffff0000u);
    float r0 = x0 - h0;
    float r1 = x1 - h1;
    asm("cvt.rn.bf16x2.f32 %0, %1, %2;" : "=r"(lp) : "f"(r1), "f"(r0));
}

__device__ __forceinline__ void mma16(float* d, const uint32_t* a, const uint32_t* b)
{
    asm volatile(
        "mma.sync.aligned.m16n8k16.row.col.f32.bf16.bf16.f32 "
        "{%0,%1,%2,%3},{%4,%5,%6,%7},{%8,%9},{%0,%1,%2,%3};"
        : "+f"(d[0]), "+f"(d[1]), "+f"(d[2]), "+f"(d[3])
        : "r"(a[0]), "r"(a[1]), "r"(a[2]), "r"(a[3]), "r"(b[0]), "r"(b[1]));
}

// ================= bf16-split NT GEMM =================
// C[M,N] = epilogue( alpha * A[M,K] @ B[N,K]^T ), fp32 in/out.
// 512 threads = 16 warps, warp grid (BM/WM)x(BN/WN) == 16.
// Smem: packed bf16x2 pairs, [row][pair] stride SDP=BK/2+4 (conflict-free LDS).
// Single smem buffer, register-staged prefetch (split happens once, at store).
template<int BM,int BN,int BK,int WM,int WN,bool RELU,bool BIAS,bool RES>
__global__ __launch_bounds__(512,1)
void bgemm_k(const float* __restrict__ A, int lda,
             const float* __restrict__ Bm, int ldb,
             float*       __restrict__ C,  int ldc,
             int K, float alpha,
             const float* __restrict__ bias,
             const float* __restrict__ res,
             int zdiv,
             long soA, long siA, long soB, long siB, long soC, long siC)
{
    constexpr int SDP = BK/2 + 4;          // uint32 pairs per row (stride 20 for BK=32)
    constexpr int MT  = WM / 16;
    constexpr int NT2 = WN / 8;
    constexpr int MW  = BM / WM;
    constexpr int KV  = BK / 4;
    constexpr int NAc = (BM * KV) / 512;   // float4 chunks per thread, A
    constexpr int NBc = (BN * KV) / 512;

    __shared__ uint32_t sAh[BM*SDP], sAl[BM*SDP];
    __shared__ uint32_t sBh[BN*SDP], sBl[BN*SDP];

    const int z  = blockIdx.z;
    const long zo = z / zdiv, zi = z % zdiv;
    A  += zo*soA + zi*siA;
    Bm += zo*soB + zi*siB;
    C  += zo*soC + zi*siC;

    const int tid    = threadIdx.x;
    const int lane   = tid & 31;
    const int warpId = tid >> 5;
    const int wm     = warpId % MW;
    const int wn     = warpId / MW;
    const int r      = lane >> 2;
    const int c      = lane & 3;
    const int rowBase = blockIdx.y * BM;
    const int colBase = blockIdx.x * BN;

    // per-thread tile-load coordinates (float4 chunks along K)
    int aR[NAc], aP[NAc];       // row, pair-base (chunk covers pairs aP, aP+1)
    #pragma unroll
    for (int j = 0; j < NAc; j++) {
        int i = tid + j*512;
        aR[j] = i / KV;
        aP[j] = (i % KV) * 2;
    }
    int bR[NBc], bP[NBc];
    #pragma unroll
    for (int j = 0; j < NBc; j++) {
        int i = tid + j*512;
        bR[j] = i / KV;
        bP[j] = (i % KV) * 2;
    }

    float acc[MT][NT2][4];
    #pragma unroll
    for (int im = 0; im < MT; im++)
        #pragma unroll
        for (int in = 0; in < NT2; in++)
            #pragma unroll
            for (int q = 0; q < 4; q++) acc[im][in][q] = 0.f;

    float4 ra[NAc], rb[NBc];
    const int nT = K / BK;

    // ---- prologue: load + split-store tile 0 ----
    #pragma unroll
    for (int j = 0; j < NAc; j++)
        ra[j] = *(const float4*)(A + (long)(rowBase + aR[j])*lda + aP[j]*2);
    #pragma unroll
    for (int j = 0; j < NBc; j++)
        rb[j] = *(const float4*)(Bm + (long)(colBase + bR[j])*ldb + bP[j]*2);
    #pragma unroll
    for (int j = 0; j < NAc; j++) {
        uint32_t h0,l0,h1,l1;
        bsplit2(ra[j].x, ra[j].y, h0, l0);
        bsplit2(ra[j].z, ra[j].w, h1, l1);
        sAh[aR[j]*SDP + aP[j]    ] = h0;  sAl[aR[j]*SDP + aP[j]    ] = l0;
        sAh[aR[j]*SDP + aP[j] + 1] = h1;  sAl[aR[j]*SDP + aP[j] + 1] = l1;
    }
    #pragma unroll
    for (int j = 0; j < NBc; j++) {
        uint32_t h0,l0,h1,l1;
        bsplit2(rb[j].x, rb[j].y, h0, l0);
        bsplit2(rb[j].z, rb[j].w, h1, l1);
        sBh[bR[j]*SDP + bP[j]    ] = h0;  sBl[bR[j]*SDP + bP[j]    ] = l0;
        sBh[bR[j]*SDP + bP[j] + 1] = h1;  sBl[bR[j]*SDP + bP[j] + 1] = l1;
    }
    __syncthreads();

    for (int t = 0; t < nT; t++) {
        const bool has_next = (t + 1) < nT;
        // prefetch next tile into registers (overlaps compute)
        if (has_next) {
            const int kn = (t + 1) * BK;
            #pragma unroll
            for (int j = 0; j < NAc; j++)
                ra[j] = *(const float4*)(A + (long)(rowBase + aR[j])*lda + (kn + aP[j]*2));
            #pragma unroll
            for (int j = 0; j < NBc; j++)
                rb[j] = *(const float4*)(Bm + (long)(colBase + bR[j])*ldb + (kn + bP[j]*2));
        }

        // compute: BK/16 ksteps of m16n8k16, 3-MMA split each
        #pragma unroll
        for (int ks = 0; ks < BK/16; ks++) {
            const int pb = ks * 8;     // pair base of this kstep
            uint32_t afh[MT][4], afl[MT][4], bfh[NT2][2], bfl[NT2][2];
            #pragma unroll
            for (int im = 0; im < MT; im++) {
                const int mb = wm*WM + im*16;
                afh[im][0] = sAh[(mb+r  )*SDP + pb + c    ];
                afh[im][1] = sAh[(mb+r+8)*SDP + pb + c    ];
                afh[im][2] = sAh[(mb+r  )*SDP + pb + c + 4];
                afh[im][3] = sAh[(mb+r+8)*SDP + pb + c + 4];
                afl[im][0] = sAl[(mb+r  )*SDP + pb + c    ];
                afl[im][1] = sAl[(mb+r+8)*SDP + pb + c    ];
                afl[im][2] = sAl[(mb+r  )*SDP + pb + c + 4];
                afl[im][3] = sAl[(mb+r+8)*SDP + pb + c + 4];
            }
            #pragma unroll
            for (int in = 0; in < NT2; in++) {
                const int nb = wn*WN + in*8;
                bfh[in][0] = sBh[(nb+r)*SDP + pb + c    ];
                bfh[in][1] = sBh[(nb+r)*SDP + pb + c + 4];
                bfl[in][0] = sBl[(nb+r)*SDP + pb + c    ];
                bfl[in][1] = sBl[(nb+r)*SDP + pb + c + 4];
            }
            #pragma unroll
            for (int im = 0; im < MT; im++)
                #pragma unroll
                for (int in = 0; in < NT2; in++) {
                    mma16(acc[im][in], afh[im], bfh[in]);  // hi*hi
                    mma16(acc[im][in], afh[im], bfl[in]);  // hi*lo
                    mma16(acc[im][in], afl[im], bfh[in]);  // lo*hi
                }
        }
        __syncthreads();

        if (has_next) {
            #pragma unroll
            for (int j = 0; j < NAc; j++) {
                uint32_t h0,l0,h1,l1;
                bsplit2(ra[j].x, ra[j].y, h0, l0);
                bsplit2(ra[j].z, ra[j].w, h1, l1);
                sAh[aR[j]*SDP + aP[j]    ] = h0;  sAl[aR[j]*SDP + aP[j]    ] = l0;
                sAh[aR[j]*SDP + aP[j] + 1] = h1;  sAl[aR[j]*SDP + aP[j] + 1] = l1;
            }
            #pragma unroll
            for (int j = 0; j < NBc; j++) {
                uint32_t h0,l0,h1,l1;
                bsplit2(rb[j].x, rb[j].y, h0, l0);
                bsplit2(rb[j].z, rb[j].w, h1, l1);
                sBh[bR[j]*SDP + bP[j]    ] = h0;  sBl[bR[j]*SDP + bP[j]    ] = l0;
                sBh[bR[j]*SDP + bP[j] + 1] = h1;  sBl[bR[j]*SDP + bP[j] + 1] = l1;
            }
            __syncthreads();
        }
    }

    // ---- epilogue ----
    #pragma unroll
    for (int im = 0; im < MT; im++) {
        #pragma unroll
        for (int in = 0; in < NT2; in++) {
            const long row0 = rowBase + wm*WM + im*16 + r;
            const long row1 = row0 + 8;
            const int  col  = colBase + wn*WN + in*8 + 2*c;
            float2 d0 = make_float2(acc[im][in][0]*alpha, acc[im][in][1]*alpha);
            float2 d1 = make_float2(acc[im][in][2]*alpha, acc[im][in][3]*alpha);
            if (BIAS) {
                float2 bv = *(const float2*)(bias + col);
                d0.x += bv.x; d0.y += bv.y; d1.x += bv.x; d1.y += bv.y;
            }
            if (RES) {
                float2 r0 = *(const float2*)(res + row0*(long)ldc + col);
                float2 r1 = *(const float2*)(res + row1*(long)ldc + col);
                d0.x += r0.x; d0.y += r0.y; d1.x += r1.x; d1.y += r1.y;
            }
            if (RELU) {
                d0.x = fmaxf(d0.x, 0.f); d0.y = fmaxf(d0.y, 0.f);
                d1.x = fmaxf(d1.x, 0.f); d1.y = fmaxf(d1.y, 0.f);
            }
            *(float2*)(C + row0*(long)ldc + col) = d0;
            *(float2*)(C + row1*(long)ldc + col) = d1;
        }
    }
}

// ================= tf32 path (kept verbatim for ctx NN GEMM; passed twice) ===
__device__ __forceinline__ void tf32split(float x, uint32_t& hi, uint32_t& lo)
{
    uint32_t h;
    asm("cvt.rna.tf32.f32 %0, %1;" : "=r"(h) : "f"(x));
    float hf = __uint_as_float(h);
    float r  = x - hf;
    uint32_t l;
    asm("cvt.rna.tf32.f32 %0, %1;" : "=r"(l) : "f"(r));
    hi = h; lo = l;
}

__device__ __forceinline__ void mma8(float* d, const uint32_t* a, const uint32_t* b)
{
    asm volatile(
        "mma.sync.aligned.m16n8k8.row.col.f32.tf32.tf32.f32 "
        "{%0,%1,%2,%3},{%4,%5,%6,%7},{%8,%9},{%0,%1,%2,%3};"
        : "+f"(d[0]), "+f"(d[1]), "+f"(d[2]), "+f"(d[3])
        : "r"(a[0]), "r"(a[1]), "r"(a[2]), "r"(a[3]), "r"(b[0]), "r"(b[1]));
}

__device__ __forceinline__ void cpasync16(uint32_t dst_smem, const float* src)
{
    asm volatile("cp.async.cg.shared.global [%0], [%1], 16;\n"
                 :: "r"(dst_smem), "l"((unsigned long long)(uintptr_t)src)
                 : "memory");
}
__device__ __forceinline__ void cpasync_commit()
{
    asm volatile("cp.async.commit_group;\n" ::: "memory");
}
__device__ __forceinline__ void cpasync_wait_all()
{
    asm volatile("cp.async.wait_group 0;\n" ::: "memory");
}

template<int BM,int BN,int BK,int WM,int WN,bool BT,bool RELU,bool BIAS,bool RES>
__global__ __launch_bounds__(256,1)
void mgemm_k(const float* __restrict__ A, int lda,
             const float* __restrict__ Bm, int ldb,
             float*       __restrict__ C,  int ldc,
             int K, float alpha,
             const float* __restrict__ bias,
             const float* __restrict__ res,
             int zdiv,
             long soA, long siA, long soB, long siB, long soC, long siC)
{
    constexpr int SDA = BK + 4;
    constexpr int SDB = BT ? (BK + 4) : (BN + 8);
    constexpr int ASZ = BM * SDA;
    constexpr int BSZ = BT ? (BN * SDB) : (BK * SDB);
    constexpr int MT  = WM / 16;
    constexpr int NT2 = WN / 8;
    constexpr int MW  = BM / WM;
    constexpr int KV  = BK / 4;
    constexpr int NAc = (BM * KV) / 256;
    constexpr int NBc = BT ? (BN * KV) / 256 : (BK * (BN/4)) / 256;

    __shared__ float sA[2*ASZ];
    __shared__ float sB[2*BSZ];

    const int z  = blockIdx.z;
    const long zo = z / zdiv, zi = z % zdiv;
    A  += zo*soA + zi*siA;
    Bm += zo*soB + zi*siB;
    C  += zo*soC + zi*siC;

    const int tid    = threadIdx.x;
    const int lane   = tid & 31;
    const int warpId = tid >> 5;
    const int wm     = warpId % MW;
    const int wn     = warpId / MW;
    const int r      = lane >> 2;
    const int c      = lane & 3;
    const int rowBase = blockIdx.y * BM;
    const int colBase = blockIdx.x * BN;

    const uint32_t sAaddr = (uint32_t)__cvta_generic_to_shared(sA);
    const uint32_t sBaddr = (uint32_t)__cvta_generic_to_shared(sB);

    int aR[NAc], aK[NAc];
    #pragma unroll
    for (int j = 0; j < NAc; j++) {
        int i = tid + j*256;
        aR[j] = i / KV; aK[j] = (i % KV) * 4;
    }
    int bR[NBc], bK[NBc];
    #pragma unroll
    for (int j = 0; j < NBc; j++) {
        int i = tid + j*256;
        if (BT) { bR[j] = i / KV;       bK[j] = (i % KV) * 4; }
        else    { bR[j] = i / (BN/4);   bK[j] = (i % (BN/4)) * 4; }
    }

    float acc[MT][NT2][4];
    #pragma unroll
    for (int im = 0; im < MT; im++)
        #pragma unroll
        for (int in = 0; in < NT2; in++)
            #pragma unroll
            for (int q = 0; q < 4; q++) acc[im][in][q] = 0.f;

    const int nT = K / BK;

    #pragma unroll
    for (int j = 0; j < NAc; j++)
        cpasync16(sAaddr + (aR[j]*SDA + aK[j])*4,
                  A + (long)(rowBase + aR[j])*lda + aK[j]);
    #pragma unroll
    for (int j = 0; j < NBc; j++) {
        if (BT)
            cpasync16(sBaddr + (bR[j]*SDB + bK[j])*4,
                      Bm + (long)(colBase + bR[j])*ldb + bK[j]);
        else
            cpasync16(sBaddr + (bR[j]*SDB + bK[j])*4,
                      Bm + (long)(bR[j])*ldb + (colBase + bK[j]));
    }
    cpasync_commit();

    for (int t = 0; t < nT; t++) {
        cpasync_wait_all();
        __syncthreads();

        if (t + 1 < nT) {
            const int kn = (t + 1) * BK;
            const uint32_t stOff = ((t + 1) & 1) ? 1u : 0u;
            const uint32_t aBase = sAaddr + stOff*ASZ*4;
            const uint32_t bBase = sBaddr + stOff*BSZ*4;
            #pragma unroll
            for (int j = 0; j < NAc; j++)
                cpasync16(aBase + (aR[j]*SDA + aK[j])*4,
                          A + (long)(rowBase + aR[j])*lda + (kn + aK[j]));
            #pragma unroll
            for (int j = 0; j < NBc; j++) {
                if (BT)
                    cpasync16(bBase + (bR[j]*SDB + bK[j])*4,
                              Bm + (long)(colBase + bR[j])*ldb + (kn + bK[j]));
                else
                    cpasync16(bBase + (bR[j]*SDB + bK[j])*4,
                              Bm + (long)(kn + bR[j])*ldb + (colBase + bK[j]));
            }
            cpasync_commit();
        }

        const float* sAb = sA + (t & 1) * ASZ;
        const float* sBb = sB + (t & 1) * BSZ;

        #pragma unroll
        for (int ks = 0; ks < BK/8; ks++) {
            const int kb = ks * 8;
            uint32_t afh[MT][4], afl[MT][4], bfh[NT2][2], bfl[NT2][2];
            #pragma unroll
            for (int im = 0; im < MT; im++) {
                const int mb = wm*WM + im*16;
                float a0 = sAb[(mb+r  )*SDA + kb + c    ];
                float a1 = sAb[(mb+r+8)*SDA + kb + c    ];
                float a2 = sAb[(mb+r  )*SDA + kb + c + 4];
                float a3 = sAb[(mb+r+8)*SDA + kb + c + 4];
                tf32split(a0, afh[im][0], afl[im][0]);
                tf32split(a1, afh[im][1], afl[im][1]);
                tf32split(a2, afh[im][2], afl[im][2]);
                tf32split(a3, afh[im][3], afl[im][3]);
            }
            #pragma unroll
            for (int in = 0; in < NT2; in++) {
                const int nb = wn*WN + in*8;
                float b0, b1;
                if (BT) {
                    b0 = sBb[(nb+r)*SDB + kb + c    ];
                    b1 = sBb[(nb+r)*SDB + kb + c + 4];
                } else {
                    b0 = sBb[(kb + c    )*SDB + nb + r];
                    b1 = sBb[(kb + c + 4)*SDB + nb + r];
                }
                tf32split(b0, bfh[in][0], bfl[in][0]);
                tf32split(b1, bfh[in][1], bfl[in][1]);
            }
            #pragma unroll
            for (int im = 0; im < MT; im++)
                #pragma unroll
                for (int in = 0; in < NT2; in++) {
                    mma8(acc[im][in], afh[im], bfh[in]);
                    mma8(acc[im][in], afh[im], bfl[in]);
                    mma8(acc[im][in], afl[im], bfh[in]);
                }
        }
    }

    #pragma unroll
    for (int im = 0; im < MT; im++) {
        #pragma unroll
        for (int in = 0; in < NT2; in++) {
            const long row0 = rowBase + wm*WM + im*16 + r;
            const long row1 = row0 + 8;
            const int  col  = colBase + wn*WN + in*8 + 2*c;
            float2 d0 = make_float2(acc[im][in][0]*alpha, acc[im][in][1]*alpha);
            float2 d1 = make_float2(acc[im][in][2]*alpha, acc[im][in][3]*alpha);
            if (BIAS) {
                float2 bv = *(const float2*)(bias + col);
                d0.x += bv.x; d0.y += bv.y; d1.x += bv.x; d1.y += bv.y;
            }
            if (RES) {
                float2 r0 = *(const float2*)(res + row0*(long)ldc + col);
                float2 r1 = *(const float2*)(res + row1*(long)ldc + col);
                d0.x += r0.x; d0.y += r0.y; d1.x += r1.x; d1.y += r1.y;
            }
            if (RELU) {
                d0.x = fmaxf(d0.x, 0.f); d0.y = fmaxf(d0.y, 0.f);
                d1.x = fmaxf(d1.x, 0.f); d1.y = fmaxf(d1.y, 0.f);
            }
            *(float2*)(C + row0*(long)ldc + col) = d0;
            *(float2*)(C + row1*(long)ldc + col) = d1;
        }
    }
}

// ---------------- softmax over rows of length 2048 (input already relu'd) ----
__global__ void softmax_k(float* __restrict__ Sc)
{
    const long row = blockIdx.x;
    float* p = Sc + row * (long)SS;
    const int tid = threadIdx.x;
    float4 v0 = ((const float4*)p)[tid];
    float4 v1 = ((const float4*)p)[tid + 256];

    float m = fmaxf(fmaxf(fmaxf(v0.x,v0.y), fmaxf(v0.z,v0.w)),
                    fmaxf(fmaxf(v1.x,v1.y), fmaxf(v1.z,v1.w)));
    #pragma unroll
    for (int o = 16; o; o >>= 1) m = fmaxf(m, __shfl_xor_sync(0xffffffffu, m, o));

    __shared__ float smax[8], ssum[8];
    const int wid = tid >> 5, lid = tid & 31;
    if (lid == 0) smax[wid] = m;
    __syncthreads();
    m = smax[0];
    #pragma unroll
    for (int i = 1; i < 8; i++) m = fmaxf(m, smax[i]);

    float e[8];
    e[0]=__expf(v0.x-m); e[1]=__expf(v0.y-m); e[2]=__expf(v0.z-m); e[3]=__expf(v0.w-m);
    e[4]=__expf(v1.x-m); e[5]=__expf(v1.y-m); e[6]=__expf(v1.z-m); e[7]=__expf(v1.w-m);
    float s = ((e[0]+e[1])+(e[2]+e[3])) + ((e[4]+e[5])+(e[6]+e[7]));
    #pragma unroll
    for (int o = 16; o; o >>= 1) s += __shfl_xor_sync(0xffffffffu, s, o);
    if (lid == 0) ssum[wid] = s;
    __syncthreads();
    s = ssum[0];
    #pragma unroll
    for (int i = 1; i < 8; i++) s += ssum[i];

    const float inv = 1.0f / s;
    ((float4*)p)[tid]       = make_float4(e[0]*inv, e[1]*inv, e[2]*inv, e[3]*inv);
    ((float4*)p)[tid + 256] = make_float4(e[4]*inv, e[5]*inv, e[6]*inv, e[7]*inv);
}

// ---------------- layernorm over rows of length 1024 ----------------
__global__ void ln_k(const float* __restrict__ in, float* __restrict__ out,
                     const float* __restrict__ gw, const float* __restrict__ bw)
{
    const long row = blockIdx.x;
    const float* p = in + row * (long)DD;
    const int tid = threadIdx.x;
    float4 v = ((const float4*)p)[tid];
    float s = v.x + v.y + v.z + v.w;
    float q = v.x*v.x + v.y*v.y + v.z*v.z + v.w*v.w;
    #pragma unroll
    for (int o = 16; o; o >>= 1) {
        s += __shfl_xor_sync(0xffffffffu, s, o);
        q += __shfl_xor_sync(0xffffffffu, q, o);
    }
    __shared__ float ss[8], qq[8];
    const int wid = tid >> 5, lid = tid & 31;
    if (lid == 0) { ss[wid] = s; qq[wid] = q; }
    __syncthreads();
    float S = 0.f, Q = 0.f;
    #pragma unroll
    for (int i = 0; i < 8; i++) { S += ss[i]; Q += qq[i]; }

    const float mean = S * (1.0f / DD);
    const float var  = Q * (1.0f / DD) - mean * mean;
    const float inv  = rsqrtf(var + 1e-5f);

    float4 g4 = ((const float4*)gw)[tid];
    float4 b4 = ((const float4*)bw)[tid];
    float4 o;
    o.x = (v.x - mean) * inv * g4.x + b4.x;
    o.y = (v.y - mean) * inv * g4.y + b4.y;
    o.z = (v.z - mean) * inv * g4.z + b4.z;
    o.w = (v.w - mean) * inv * g4.w + b4.w;
    ((float4*)(out + row * (long)DD))[tid] = o;
}

// ---------------- launch ----------------
extern "C" void kernel_launch(void* const* d_in, const int* in_sizes, int n_in,
                              void* d_out, int out_size)
{
    const float* X   = (const float*)d_in[0];
    const float* Wq  = (const float*)d_in[1];
    const float* Wk  = (const float*)d_in[2];
    const float* Wo  = (const float*)d_in[3];
    const float* l1g = (const float*)d_in[4];
    const float* l1b = (const float*)d_in[5];
    const float* l2g = (const float*)d_in[6];
    const float* l2b = (const float*)d_in[7];
    const float* W1  = (const float*)d_in[8];
    const float* b1  = (const float*)d_in[9];
    const float* W2  = (const float*)d_in[10];
    const float* b2  = (const float*)d_in[11];
    float* out = (float*)d_out;

    float *Q, *K, *V, *Sc, *CT, *AR, *Y, *Hh, *Z;
    cudaGetSymbolAddress((void**)&Q,  g_Q);
    cudaGetSymbolAddress((void**)&K,  g_K);
    cudaGetSymbolAddress((void**)&V,  g_V);
    cudaGetSymbolAddress((void**)&Sc, g_Sc);
    cudaGetSymbolAddress((void**)&CT, g_ctx);
    cudaGetSymbolAddress((void**)&AR, g_ar);
    cudaGetSymbolAddress((void**)&Y,  g_y);
    cudaGetSymbolAddress((void**)&Hh, g_h);
    cudaGetSymbolAddress((void**)&Z,  g_z);

    const dim3 blk512(512);
    const dim3 blk256(256);
    const dim3 gproj(DD/128,  BSR/128, 1);
    const dim3 gscC (SS/128,  QC/128,  BB*HH);
    const dim3 gctxC(DHh/64,  QC/64,   BB*HH);
    const dim3 gf1  (FFD/128, BSR/128, 1);

    // --- QKV projections: Q/K = X@Wq^T / X@Wk^T, V = X@Wo^T (bf16-split NT) ---
    bgemm_k<128,128,32,32,32,false,false,false><<<gproj, blk512>>>(
        X, DD, Wq, DD, Q, DD, DD, 1.f, nullptr, nullptr, 1, 0,0,0,0,0,0);
    bgemm_k<128,128,32,32,32,false,false,false><<<gproj, blk512>>>(
        X, DD, Wk, DD, K, DD, DD, 1.f, nullptr, nullptr, 1, 0,0,0,0,0,0);
    bgemm_k<128,128,32,32,32,false,false,false><<<gproj, blk512>>>(
        X, DD, Wo, DD, V, DD, DD, 1.f, nullptr, nullptr, 1, 0,0,0,0,0,0);

    // --- attention, chunked over query rows ---
    for (int cch = 0; cch < NCHUNK; cch++) {
        // scores chunk: relu(Q[c] @ K^T / 8), batched over (b,h)
        bgemm_k<128,128,32,32,32,true,false,false><<<gscC, blk512>>>(
            Q + (long)cch*QC*DD, DD, K, DD, Sc, SS, DHh, 0.125f, nullptr, nullptr,
            HH, (long)SS*DD, (long)DHh,
                (long)SS*DD, (long)DHh,
                (long)HH*QC*SS, (long)QC*SS);

        softmax_k<<<BB*HH*QC, 256>>>(Sc);

        // ctx chunk = attn[c] @ V_h  (NN tf32 gemm, N=64) — unchanged this round
        mgemm_k<64,64,16,32,16,false,false,false,false><<<gctxC, blk256>>>(
            Sc, SS, V, DD, CT + (long)cch*QC*DD, DD, SS, 1.f, nullptr, nullptr,
            HH, (long)HH*QC*SS, (long)QC*SS,
                (long)SS*DD, (long)DHh,
                (long)SS*DD, (long)DHh);
    }

    // --- out-proj + residual X ---
    bgemm_k<128,128,32,32,32,false,false,true><<<gproj, blk512>>>(
        CT, DD, Wo, DD, AR, DD, DD, 1.f, nullptr, X, 1, 0,0,0,0,0,0);

    ln_k<<<BSR, 256>>>(AR, Y, l1g, l1b);

    // --- FFN1: relu(y @ W1^T + b1) ---
    bgemm_k<128,128,32,32,32,true,true,false><<<gf1, blk512>>>(
        Y, DD, W1, DD, Hh, FFD, DD, 1.f, b1, nullptr, 1, 0,0,0,0,0,0);

    // --- FFN2: h @ W2^T + b2 + y ---
    bgemm_k<128,128,32,32,32,false,true,true><<<gproj, blk512>>>(
        Hh, FFD, W2, FFD, Z, DD, FFD, 1.f, b2, Y, 1, 0,0,0,0,0,0);

    ln_k<<<BSR, 256>>>(Z, out, l2g, l2b);
}